// round 6
// baseline (speedup 1.0000x reference)
#include <cuda_runtime.h>
#include <math.h>

#define NPTS 40000
#define SNBR 16
#define CDIM 96
#define GDIM 12
#define EPSF 1e-5f

// Scratch for projected features (device globals: no allocation allowed)
__device__ float g_query[NPTS * CDIM];
__device__ float g_keyf [NPTS * CDIM];
__device__ float g_val  [NPTS * CDIM];

__device__ __forceinline__ float warp_sum32(float v) {
    v += __shfl_xor_sync(0xffffffffu, v, 16);
    v += __shfl_xor_sync(0xffffffffu, v, 8);
    v += __shfl_xor_sync(0xffffffffu, v, 4);
    v += __shfl_xor_sync(0xffffffffu, v, 2);
    v += __shfl_xor_sync(0xffffffffu, v, 1);
    return v;
}
__device__ __forceinline__ float group_sum16(float v) {
    v += __shfl_xor_sync(0xffffffffu, v, 8);
    v += __shfl_xor_sync(0xffffffffu, v, 4);
    v += __shfl_xor_sync(0xffffffffu, v, 2);
    v += __shfl_xor_sync(0xffffffffu, v, 1);
    return v;
}
__device__ __forceinline__ float d4(float4 u, float4 x, float a) {
    return fmaf(u.x, x.x, fmaf(u.y, x.y, fmaf(u.z, x.z, fmaf(u.w, x.w, a))));
}

// ---------------------------------------------------------------------------
// Kernel A: fused q/k/v projections, 4 rows per warp per batch so each
// weight LDS.128 feeds 4 FMAs.
// ---------------------------------------------------------------------------
template <bool DO_LN>
__device__ __forceinline__ void proj_batch4(
    const float* __restrict__ src, float* __restrict__ dst,
    const float* Wt,            // smem, [c][100]
    const float* bias, const float* gain, const float* beta, // smem
    float* xb,                  // per-warp smem stage, 4*96 floats
    int base, int lane)
{
    const int c0 = lane, c1 = lane + 32, c2 = lane + 64;
    bool ok[4];
#pragma unroll
    for (int r = 0; r < 4; r++) {
        int row = base + r;
        ok[r] = row < NPTS;
        if (ok[r]) {
            xb[r * 96 + c0] = src[row * CDIM + c0];
            xb[r * 96 + c1] = src[row * CDIM + c1];
            xb[r * 96 + c2] = src[row * CDIM + c2];
        }
    }
    __syncwarp();
    const float4* xb4 = (const float4*)xb;
    const float4* W0 = (const float4*)(Wt + c0 * 100);
    const float4* W1 = (const float4*)(Wt + c1 * 100);
    const float4* W2 = (const float4*)(Wt + c2 * 100);
    float a0[4] = {0,0,0,0}, a1[4] = {0,0,0,0}, a2[4] = {0,0,0,0};
#pragma unroll
    for (int j4 = 0; j4 < 24; j4++) {
        float4 x0 = xb4[j4], x1 = xb4[24 + j4], x2 = xb4[48 + j4], x3 = xb4[72 + j4];
        float4 u = W0[j4];
        a0[0] = d4(u, x0, a0[0]); a0[1] = d4(u, x1, a0[1]);
        a0[2] = d4(u, x2, a0[2]); a0[3] = d4(u, x3, a0[3]);
        u = W1[j4];
        a1[0] = d4(u, x0, a1[0]); a1[1] = d4(u, x1, a1[1]);
        a1[2] = d4(u, x2, a1[2]); a1[3] = d4(u, x3, a1[3]);
        u = W2[j4];
        a2[0] = d4(u, x0, a2[0]); a2[1] = d4(u, x1, a2[1]);
        a2[2] = d4(u, x2, a2[2]); a2[3] = d4(u, x3, a2[3]);
    }
    __syncwarp();   // readers of xb done before caller restages
#pragma unroll
    for (int r = 0; r < 4; r++) {
        float y0 = a0[r] + bias[c0];
        float y1 = a1[r] + bias[c1];
        float y2 = a2[r] + bias[c2];
        if (DO_LN) {
            float mu = warp_sum32(y0 + y1 + y2) * (1.0f / 96.0f);
            float e0 = y0 - mu, e1 = y1 - mu, e2 = y2 - mu;
            float var = warp_sum32(e0*e0 + e1*e1 + e2*e2) * (1.0f / 96.0f);
            float rs = rsqrtf(var + EPSF);
            y0 = fmaxf(fmaf(e0 * rs, gain[c0], beta[c0]), 0.0f);
            y1 = fmaxf(fmaf(e1 * rs, gain[c1], beta[c1]), 0.0f);
            y2 = fmaxf(fmaf(e2 * rs, gain[c2], beta[c2]), 0.0f);
        }
        if (ok[r]) {
            int row = base + r;
            dst[row * CDIM + c0] = y0;
            dst[row * CDIM + c1] = y1;
            dst[row * CDIM + c2] = y2;
        }
    }
}

__global__ void __launch_bounds__(256, 1) proj_kernel(
    const float* __restrict__ q, const float* __restrict__ k, const float* __restrict__ v,
    const float* __restrict__ Wq, const float* __restrict__ bq,
    const float* __restrict__ gq, const float* __restrict__ betaq,
    const float* __restrict__ Wk, const float* __restrict__ bk,
    const float* __restrict__ gk, const float* __restrict__ betak,
    const float* __restrict__ Wv, const float* __restrict__ bv)
{
    extern __shared__ float sm[];
    float* Wt  = sm;                // 3 * 9600
    float* prm = sm + 28800;        // 672
    float* xst = sm + 29472;        // 8 warps * 384

    int tid = threadIdx.x;
    for (int i = tid; i < 9216; i += blockDim.x) {
        int j = i / 96, c = i % 96;
        Wt[0 * 9600 + c * 100 + j] = Wq[i];
        Wt[1 * 9600 + c * 100 + j] = Wk[i];
        Wt[2 * 9600 + c * 100 + j] = Wv[i];
    }
    for (int i = tid; i < 96; i += blockDim.x) {
        prm[i]       = bq[i];  prm[96 + i]  = gq[i];  prm[192 + i] = betaq[i];
        prm[288 + i] = bk[i];  prm[384 + i] = gk[i];  prm[480 + i] = betak[i];
        prm[576 + i] = bv[i];
    }
    __syncthreads();

    int warp = tid >> 5, lane = tid & 31;
    int gw = blockIdx.x * 8 + warp;
    int nw = gridDim.x * 8;
    float* xb = xst + warp * 384;

    for (int base = gw * 4; base < NPTS; base += nw * 4) {
        proj_batch4<true >(q, g_query, Wt,         prm,       prm + 96,  prm + 192, xb, base, lane);
        proj_batch4<true >(k, g_keyf,  Wt + 9600,  prm + 288, prm + 384, prm + 480, xb, base, lane);
        proj_batch4<false>(v, g_val,   Wt + 19200, prm + 576, prm,       prm,       xb, base, lane);
    }
}

// ---------------------------------------------------------------------------
// Kernel B: fused grouped vector attention.
// 128 threads = 4 warps. Warp pair {0,1} -> point n0, pair {2,3} -> n0+1.
// Each warp handles 8 neighbors, so every Wp2 smem load feeds 8 FMAs.
// smem (floats): Wp2t 9600 | Ww1t 1200 | Ww2 144 | wlog 384 | hbuf 3072
//   = 14400 floats = 57,600 B  -> 4 blocks/SM (matches 128-reg cap).
// ---------------------------------------------------------------------------
#define SMEMB_FLOATS 14400

__global__ void __launch_bounds__(128, 4) attn_kernel(
    const float* __restrict__ xyz, const int* __restrict__ refidx,
    const float* __restrict__ Wp1, const float* __restrict__ bp1,
    const float* __restrict__ gp,  const float* __restrict__ betap,
    const float* __restrict__ Wp2, const float* __restrict__ bp2,
    const float* __restrict__ Ww1, const float* __restrict__ bw1,
    const float* __restrict__ gw,  const float* __restrict__ betaw,
    const float* __restrict__ Ww2, const float* __restrict__ bw2,
    float* __restrict__ out)
{
    extern __shared__ float sm[];
    float* Wp2t  = sm;            // 9600  ([c][100])
    float* Ww1t  = sm + 9600;     // 1200  ([g][100])
    float* sWw2  = sm + 10800;    // 144
    float* wlog  = sm + 10944;    // 2 points * 16 nbr * 12
    float* hbuf  = sm + 11328;    // 4 warps * 768

    int tid = threadIdx.x;
    for (int i = tid; i < 9216; i += 128) {
        int j = i / 96, c = i % 96;
        Wp2t[c * 100 + j] = Wp2[i];
    }
    for (int i = tid; i < 1152; i += 128) {
        int j = i / 12, g = i % 12;
        Ww1t[g * 100 + j] = Ww1[i];
    }
    for (int i = tid; i < 144; i += 128) sWw2[i] = Ww2[i];   // FIXED: was `if (tid<144)` with 128 threads
    __syncthreads();

    int warp = tid >> 5, lane = tid & 31;
    const int c0 = lane, c1 = lane + 32, c2 = lane + 64;
    float* hb = hbuf + warp * 768;
    const float4* hb4 = (const float4*)hb;
    const float4* W0 = (const float4*)(Wp2t + c0 * 100);
    const float4* W1 = (const float4*)(Wp2t + c1 * 100);
    const float4* W2 = (const float4*)(Wp2t + c2 * 100);

    // per-lane invariants hoisted straight from gmem
    float w1_00 = Wp1[c0],      w1_10 = Wp1[96 + c0], w1_20 = Wp1[192 + c0];
    float w1_01 = Wp1[c1],      w1_11 = Wp1[96 + c1], w1_21 = Wp1[192 + c1];
    float w1_02 = Wp1[c2],      w1_12 = Wp1[96 + c2], w1_22 = Wp1[192 + c2];
    float bb0 = bp1[c0],  bb1 = bp1[c1],  bb2 = bp1[c2];
    float gp0 = gp[c0],   gp1 = gp[c1],   gp2 = gp[c2];
    float be0 = betap[c0],be1 = betap[c1],be2 = betap[c2];
    float b20 = bp2[c0],  b21 = bp2[c1],  b22 = bp2[c2];
    const int g0 = c0 >> 3, g1 = c1 >> 3, g2 = c2 >> 3;
    const int halfbit = lane & 16;
    const int gl = lane & 15;
    const bool act = gl < 12;
    const int gidx = act ? gl : 0;
    float bw1r = bw1[gidx], gwr = gw[gidx], bewr = betaw[gidx], bw2r = bw2[gidx];

    const int ppt   = warp >> 1;        // which of the 2 points this warp serves
    const int lbase = (warp & 1) * 8;   // neighbor offset within the point
    float* wl_pt = wlog + ppt * 192;

    for (int n0 = blockIdx.x * 2; n0 < NPTS; n0 += gridDim.x * 2) {
        __syncthreads();   // previous iteration fully consumed (hbuf/wlog)
        int n = n0 + ppt;

        float qr0 = g_query[n * CDIM + c0];
        float qr1 = g_query[n * CDIM + c1];
        float qr2 = g_query[n * CDIM + c2];
        float px = xyz[n * 3], py = xyz[n * 3 + 1], pz = xyz[n * 3 + 2];

        int safe[8]; float mk[8];
#pragma unroll
        for (int ss = 0; ss < 8; ss++) {
            int idx = refidx[n * SNBR + lbase + ss];
            mk[ss]  = (idx >= 0) ? 1.0f : 0.0f;
            safe[ss] = (idx >= 0) ? idx : 0;
        }
        // k-gather prefetch: in flight during phase 1 + 2
        float kgA[8], kgB[8], kgC[8];
#pragma unroll
        for (int ss = 0; ss < 8; ss++) {
            kgA[ss] = g_keyf[safe[ss] * CDIM + c0];
            kgB[ss] = g_keyf[safe[ss] * CDIM + c1];
            kgC[ss] = g_keyf[safe[ss] * CDIM + c2];
        }

        // phase 1: h = relu(ln(pos@Wp1+bp1)) for 8 neighbors -> hb
#pragma unroll
        for (int ss = 0; ss < 8; ss++) {
            int sf = safe[ss]; float m = mk[ss];
            float p0 = (xyz[sf * 3]     - px) * m;
            float p1 = (xyz[sf * 3 + 1] - py) * m;
            float p2 = (xyz[sf * 3 + 2] - pz) * m;
            float t0 = fmaf(p0, w1_00, fmaf(p1, w1_10, fmaf(p2, w1_20, bb0)));
            float t1 = fmaf(p0, w1_01, fmaf(p1, w1_11, fmaf(p2, w1_21, bb1)));
            float t2 = fmaf(p0, w1_02, fmaf(p1, w1_12, fmaf(p2, w1_22, bb2)));
            float mu = warp_sum32(t0 + t1 + t2) * (1.0f / 96.0f);
            float e0 = t0 - mu, e1 = t1 - mu, e2 = t2 - mu;
            float var = warp_sum32(e0*e0 + e1*e1 + e2*e2) * (1.0f / 96.0f);
            float rs = rsqrtf(var + EPSF);
            hb[ss * 96 + c0] = fmaxf(fmaf(e0 * rs, gp0, be0), 0.0f);
            hb[ss * 96 + c1] = fmaxf(fmaf(e1 * rs, gp1, be1), 0.0f);
            hb[ss * 96 + c2] = fmaxf(fmaf(e2 * rs, gp2, be2), 0.0f);
        }
        __syncwarp();

        // phase 2: batched peb matvec, weight reuse x8
        float a0[8] = {0,0,0,0,0,0,0,0};
        float a1[8] = {0,0,0,0,0,0,0,0};
        float a2[8] = {0,0,0,0,0,0,0,0};
#pragma unroll 6
        for (int j4 = 0; j4 < 24; j4++) {
            float4 u0 = W0[j4], u1 = W1[j4], u2 = W2[j4];
#pragma unroll
            for (int ss = 0; ss < 8; ss++) {
                float4 h = hb4[ss * 24 + j4];
                a0[ss] = d4(u0, h, a0[ss]);
                a1[ss] = d4(u1, h, a1[ss]);
                a2[ss] = d4(u2, h, a2[ss]);
            }
        }
        __syncwarp();   // hb reads done before rel overwrite

        // v-gather burst (MLP-pipelined), then epilogue
        float vgA[8], vgB[8], vgC[8];
#pragma unroll
        for (int ss = 0; ss < 8; ss++) {
            vgA[ss] = g_val[safe[ss] * CDIM + c0];
            vgB[ss] = g_val[safe[ss] * CDIM + c1];
            vgC[ss] = g_val[safe[ss] * CDIM + c2];
        }
        float vp0[8], vp1[8], vp2[8];
#pragma unroll
        for (int ss = 0; ss < 8; ss++) {
            float m = mk[ss];
            float peb0 = a0[ss] + b20, peb1 = a1[ss] + b21, peb2 = a2[ss] + b22;
            hb[ss * 96 + c0] = fmaf(kgA[ss], m, -qr0) + peb0;
            hb[ss * 96 + c1] = fmaf(kgB[ss], m, -qr1) + peb1;
            hb[ss * 96 + c2] = fmaf(kgC[ss], m, -qr2) + peb2;
            vp0[ss] = fmaf(vgA[ss], m, peb0);
            vp1[ss] = fmaf(vgB[ss], m, peb1);
            vp2[ss] = fmaf(vgC[ss], m, peb2);
        }
        __syncwarp();

        // phase 3: w-logits, both half-warps active, 2 neighbors per pass
#pragma unroll
        for (int pass = 0; pass < 4; pass++) {
            int sl = pass * 2 + (halfbit >> 4);
            float u0 = 0, u1 = 0, u2 = 0, u3 = 0;
            if (act) {
                const float4* Wg = (const float4*)(Ww1t + gl * 100);
                const float4* rv = hb4 + sl * 24;
#pragma unroll 6
                for (int j4 = 0; j4 < 24; j4++) {
                    float4 r = rv[j4], w = Wg[j4];
                    u0 = fmaf(w.x, r.x, u0); u1 = fmaf(w.y, r.y, u1);
                    u2 = fmaf(w.z, r.z, u2); u3 = fmaf(w.w, r.w, u3);
                }
            }
            float uacc = act ? (u0 + u1 + u2 + u3 + bw1r) : 0.0f;
            float mug = group_sum16(uacc) * (1.0f / 12.0f);
            float df = act ? (uacc - mug) : 0.0f;
            float varg = group_sum16(df * df) * (1.0f / 12.0f);
            float rsg = rsqrtf(varg + EPSF);
            float aval = act ? fmaxf(fmaf(df * rsg, gwr, bewr), 0.0f) : 0.0f;
            float wl = bw2r;
#pragma unroll
            for (int hh = 0; hh < 12; hh++) {
                float av = __shfl_sync(0xffffffffu, aval, halfbit | hh);
                wl = fmaf(av, sWw2[hh * 12 + gidx], wl);
            }
            if (act) wl_pt[(lbase + sl) * 12 + gl] = wl;
        }
        __syncthreads();

        // softmax over 16 neighbors per (point, group), * mask
        if (tid < 24) {
            int p = tid / 12, g = tid % 12;
            int nn = n0 + p;
            float* wp = wlog + p * 192;
            float m = -1e30f;
#pragma unroll
            for (int s = 0; s < SNBR; s++) m = fmaxf(m, wp[s * 12 + g]);
            float e[SNBR]; float sumv = 0.0f;
#pragma unroll
            for (int s = 0; s < SNBR; s++) { e[s] = expf(wp[s * 12 + g] - m); sumv += e[s]; }
            float inv = 1.0f / sumv;
#pragma unroll
            for (int s = 0; s < SNBR; s++) {
                float msk = (refidx[nn * SNBR + s] >= 0) ? 1.0f : 0.0f;
                wp[s * 12 + g] = e[s] * inv * msk;
            }
        }
        __syncthreads();

        // per-warp partial einsum over its 8 neighbors
        float f0 = 0, f1 = 0, f2 = 0;
#pragma unroll
        for (int ss = 0; ss < 8; ss++) {
            f0 = fmaf(vp0[ss], wl_pt[(lbase + ss) * 12 + g0], f0);
            f1 = fmaf(vp1[ss], wl_pt[(lbase + ss) * 12 + g1], f1);
            f2 = fmaf(vp2[ss], wl_pt[(lbase + ss) * 12 + g2], f2);
        }
        hb[c0] = f0; hb[c1] = f1; hb[c2] = f2;   // reuse hbuf as partial buffer
        __syncthreads();

        // combine warp pairs, write both points
        for (int i = tid; i < 192; i += 128) {
            int p = i / 96, c = i % 96;
            out[(n0 + p) * CDIM + c] = hbuf[(p * 2) * 768 + c] + hbuf[(p * 2 + 1) * 768 + c];
        }
    }
}

// ---------------------------------------------------------------------------
extern "C" void kernel_launch(void* const* d_in, const int* in_sizes, int n_in,
                              void* d_out, int out_size) {
    const float* q     = (const float*)d_in[0];
    const float* k     = (const float*)d_in[1];
    const float* v     = (const float*)d_in[2];
    const float* xyz   = (const float*)d_in[3];
    const int*   ridx  = (const int*)  d_in[4];
    const float* Wq    = (const float*)d_in[5];
    const float* bq    = (const float*)d_in[6];
    const float* gq    = (const float*)d_in[7];
    const float* betaq = (const float*)d_in[8];
    const float* Wk    = (const float*)d_in[9];
    const float* bk    = (const float*)d_in[10];
    const float* gk    = (const float*)d_in[11];
    const float* betak = (const float*)d_in[12];
    const float* Wv    = (const float*)d_in[13];
    const float* bv    = (const float*)d_in[14];
    const float* Wp1   = (const float*)d_in[15];
    const float* bp1   = (const float*)d_in[16];
    const float* gp    = (const float*)d_in[17];
    const float* betap = (const float*)d_in[18];
    const float* Wp2   = (const float*)d_in[19];
    const float* bp2   = (const float*)d_in[20];
    const float* Ww1   = (const float*)d_in[21];
    const float* bw1   = (const float*)d_in[22];
    const float* gw    = (const float*)d_in[23];
    const float* betaw = (const float*)d_in[24];
    const float* Ww2   = (const float*)d_in[25];
    const float* bw2   = (const float*)d_in[26];
    float* out = (float*)d_out;

    size_t smemA = (size_t)(28800 + 672 + 8 * 384) * sizeof(float);   // ~130 KB
    size_t smemB = (size_t)SMEMB_FLOATS * sizeof(float);              // 57,600 B
    cudaFuncSetAttribute(proj_kernel, cudaFuncAttributeMaxDynamicSharedMemorySize, (int)smemA);
    cudaFuncSetAttribute(attn_kernel, cudaFuncAttributeMaxDynamicSharedMemorySize, (int)smemB);

    proj_kernel<<<148, 256, smemA>>>(q, k, v, Wq, bq, gq, betaq, Wk, bk, gk, betak, Wv, bv);
    attn_kernel<<<592, 128, smemB>>>(xyz, ridx, Wp1, bp1, gp, betap, Wp2, bp2,
                                     Ww1, bw1, gw, betaw, Ww2, bw2, out);
}

// round 8
// speedup vs baseline: 1.4039x; 1.4039x over previous
#include <cuda_runtime.h>
#include <math.h>

#define NPTS 40000
#define SNBR 16
#define CDIM 96
#define GDIM 12
#define EPSF 1e-5f

// Scratch for projected features (device globals: no allocation allowed)
__device__ float g_query[NPTS * CDIM];
__device__ float g_keyf [NPTS * CDIM];
__device__ float g_val  [NPTS * CDIM];

__device__ __forceinline__ float warp_sum32(float v) {
    v += __shfl_xor_sync(0xffffffffu, v, 16);
    v += __shfl_xor_sync(0xffffffffu, v, 8);
    v += __shfl_xor_sync(0xffffffffu, v, 4);
    v += __shfl_xor_sync(0xffffffffu, v, 2);
    v += __shfl_xor_sync(0xffffffffu, v, 1);
    return v;
}
__device__ __forceinline__ float group_sum16(float v) {
    v += __shfl_xor_sync(0xffffffffu, v, 8);
    v += __shfl_xor_sync(0xffffffffu, v, 4);
    v += __shfl_xor_sync(0xffffffffu, v, 2);
    v += __shfl_xor_sync(0xffffffffu, v, 1);
    return v;
}
__device__ __forceinline__ float d4(float4 u, float4 x, float a) {
    return fmaf(u.x, x.x, fmaf(u.y, x.y, fmaf(u.z, x.z, fmaf(u.w, x.w, a))));
}

// ---------------------------------------------------------------------------
// Kernel A: q/k/v projections, one weight matrix per block type so each
// block needs only 51,840 B smem -> 3 resident blocks/SM in one wave.
// 4 rows per warp per batch so each weight LDS.128 feeds 4 FMAs.
// ---------------------------------------------------------------------------
__device__ __forceinline__ void proj_batch4(
    const float* __restrict__ src, float* __restrict__ dst,
    const float* Wt,            // smem, [c][100]
    const float* bias, const float* gain, const float* beta, // smem
    float* xb,                  // per-warp smem stage, 4*96 floats
    int base, int lane, bool do_ln)
{
    const int c0 = lane, c1 = lane + 32, c2 = lane + 64;
    bool ok[4];
#pragma unroll
    for (int r = 0; r < 4; r++) {
        int row = base + r;
        ok[r] = row < NPTS;
        if (ok[r]) {
            xb[r * 96 + c0] = src[row * CDIM + c0];
            xb[r * 96 + c1] = src[row * CDIM + c1];
            xb[r * 96 + c2] = src[row * CDIM + c2];
        }
    }
    __syncwarp();
    const float4* xb4 = (const float4*)xb;
    const float4* W0 = (const float4*)(Wt + c0 * 100);
    const float4* W1 = (const float4*)(Wt + c1 * 100);
    const float4* W2 = (const float4*)(Wt + c2 * 100);
    float a0[4] = {0,0,0,0}, a1[4] = {0,0,0,0}, a2[4] = {0,0,0,0};
#pragma unroll
    for (int j4 = 0; j4 < 24; j4++) {
        float4 x0 = xb4[j4], x1 = xb4[24 + j4], x2 = xb4[48 + j4], x3 = xb4[72 + j4];
        float4 u = W0[j4];
        a0[0] = d4(u, x0, a0[0]); a0[1] = d4(u, x1, a0[1]);
        a0[2] = d4(u, x2, a0[2]); a0[3] = d4(u, x3, a0[3]);
        u = W1[j4];
        a1[0] = d4(u, x0, a1[0]); a1[1] = d4(u, x1, a1[1]);
        a1[2] = d4(u, x2, a1[2]); a1[3] = d4(u, x3, a1[3]);
        u = W2[j4];
        a2[0] = d4(u, x0, a2[0]); a2[1] = d4(u, x1, a2[1]);
        a2[2] = d4(u, x2, a2[2]); a2[3] = d4(u, x3, a2[3]);
    }
    __syncwarp();   // readers of xb done before caller restages
#pragma unroll
    for (int r = 0; r < 4; r++) {
        float y0 = a0[r] + bias[c0];
        float y1 = a1[r] + bias[c1];
        float y2 = a2[r] + bias[c2];
        if (do_ln) {
            float mu = warp_sum32(y0 + y1 + y2) * (1.0f / 96.0f);
            float e0 = y0 - mu, e1 = y1 - mu, e2 = y2 - mu;
            float var = warp_sum32(e0*e0 + e1*e1 + e2*e2) * (1.0f / 96.0f);
            float rs = rsqrtf(var + EPSF);
            y0 = fmaxf(fmaf(e0 * rs, gain[c0], beta[c0]), 0.0f);
            y1 = fmaxf(fmaf(e1 * rs, gain[c1], beta[c1]), 0.0f);
            y2 = fmaxf(fmaf(e2 * rs, gain[c2], beta[c2]), 0.0f);
        }
        if (ok[r]) {
            int row = base + r;
            dst[row * CDIM + c0] = y0;
            dst[row * CDIM + c1] = y1;
            dst[row * CDIM + c2] = y2;
        }
    }
}

__global__ void __launch_bounds__(256, 3) proj_kernel(
    const float* __restrict__ q, const float* __restrict__ k, const float* __restrict__ v,
    const float* __restrict__ Wq, const float* __restrict__ bq,
    const float* __restrict__ gq, const float* __restrict__ betaq,
    const float* __restrict__ Wk, const float* __restrict__ bk,
    const float* __restrict__ gk, const float* __restrict__ betak,
    const float* __restrict__ Wv, const float* __restrict__ bv)
{
    extern __shared__ float sm[];
    float* Wt  = sm;            // 9600
    float* prm = sm + 9600;     // 288
    float* xst = sm + 9888;     // 8 warps * 384
    // total 12,960 floats = 51,840 B

    int type = blockIdx.x / 148;   // 0=q, 1=k, 2=v
    int blk  = blockIdx.x % 148;
    const float *src, *W, *bias, *gain, *beta;
    float* dst;
    bool do_ln;
    if (type == 0) { src = q; W = Wq; bias = bq; gain = gq; beta = betaq; dst = g_query; do_ln = true;  }
    else if (type == 1) { src = k; W = Wk; bias = bk; gain = gk; beta = betak; dst = g_keyf; do_ln = true;  }
    else { src = v; W = Wv; bias = bv; gain = bv; beta = bv; dst = g_val; do_ln = false; }

    int tid = threadIdx.x;
    for (int i = tid; i < 9216; i += 256) {
        int j = i / 96, c = i % 96;
        Wt[c * 100 + j] = W[i];
    }
    for (int i = tid; i < 96; i += 256) {
        prm[i]       = bias[i];
        prm[96 + i]  = do_ln ? gain[i] : 0.0f;
        prm[192 + i] = do_ln ? beta[i] : 0.0f;
    }
    __syncthreads();

    int warp = tid >> 5, lane = tid & 31;
    float* xb = xst + warp * 384;

    for (int base = (blk * 8 + warp) * 4; base < NPTS; base += 148 * 8 * 4) {
        proj_batch4(src, dst, Wt, prm, prm + 96, prm + 192, xb, base, lane, do_ln);
    }
}

// ---------------------------------------------------------------------------
// Kernel B: fused grouped vector attention.
// 128 threads = 4 warps. Warp pair {0,1} -> point n0, pair {2,3} -> n0+1.
// Each warp handles 8 neighbors, so every Wp2 smem load feeds 8 FMAs.
// smem (floats): Wp2t 9600 (Ww2 stashed in row padding) | Ww1t 1200 |
//   wlog 384 | hbuf 3072 = 14,256 floats = 57,024 B
//   -> (57,024 + 1,024 reserved) * 4 = 232,192 <= 233,472 : 4 blocks/SM.
// ---------------------------------------------------------------------------
#define SMEMB_FLOATS 14256
// Ww2[i] stashed at Wp2t row-padding slot:
#define SWW2(i) sm[(((i) >> 1) * 100) + 96 + ((i) & 1)]

__global__ void __launch_bounds__(128, 4) attn_kernel(
    const float* __restrict__ xyz, const int* __restrict__ refidx,
    const float* __restrict__ Wp1, const float* __restrict__ bp1,
    const float* __restrict__ gp,  const float* __restrict__ betap,
    const float* __restrict__ Wp2, const float* __restrict__ bp2,
    const float* __restrict__ Ww1, const float* __restrict__ bw1,
    const float* __restrict__ gw,  const float* __restrict__ betaw,
    const float* __restrict__ Ww2, const float* __restrict__ bw2,
    float* __restrict__ out)
{
    extern __shared__ float sm[];
    float* Wp2t  = sm;            // 9600  ([c][100], floats 96..99/row hold Ww2)
    float* Ww1t  = sm + 9600;     // 1200  ([g][100])
    float* wlog  = sm + 10800;    // 2 points * 16 nbr * 12
    float* hbuf  = sm + 11184;    // 4 warps * 768

    int tid = threadIdx.x;
    for (int i = tid; i < 9216; i += 128) {
        int j = i / 96, c = i % 96;
        Wp2t[c * 100 + j] = Wp2[i];
    }
    for (int i = tid; i < 1152; i += 128) {
        int j = i / 12, g = i % 12;
        Ww1t[g * 100 + j] = Ww1[i];
    }
    for (int i = tid; i < 144; i += 128) SWW2(i) = Ww2[i];
    __syncthreads();

    int warp = tid >> 5, lane = tid & 31;
    const int c0 = lane, c1 = lane + 32, c2 = lane + 64;
    float* hb = hbuf + warp * 768;
    const float4* hb4 = (const float4*)hb;
    const float4* W0 = (const float4*)(Wp2t + c0 * 100);
    const float4* W1 = (const float4*)(Wp2t + c1 * 100);
    const float4* W2 = (const float4*)(Wp2t + c2 * 100);

    // per-lane invariants hoisted straight from gmem
    float w1_00 = Wp1[c0],      w1_10 = Wp1[96 + c0], w1_20 = Wp1[192 + c0];
    float w1_01 = Wp1[c1],      w1_11 = Wp1[96 + c1], w1_21 = Wp1[192 + c1];
    float w1_02 = Wp1[c2],      w1_12 = Wp1[96 + c2], w1_22 = Wp1[192 + c2];
    float bb0 = bp1[c0],  bb1 = bp1[c1],  bb2 = bp1[c2];
    float gp0 = gp[c0],   gp1 = gp[c1],   gp2 = gp[c2];
    float be0 = betap[c0],be1 = betap[c1],be2 = betap[c2];
    float b20 = bp2[c0],  b21 = bp2[c1],  b22 = bp2[c2];
    const int g0 = c0 >> 3, g1 = c1 >> 3, g2 = c2 >> 3;
    const int halfbit = lane & 16;
    const int gl = lane & 15;
    const bool act = gl < 12;
    const int gidx = act ? gl : 0;
    float bw1r = bw1[gidx], gwr = gw[gidx], bewr = betaw[gidx], bw2r = bw2[gidx];

    const int ppt   = warp >> 1;        // which of the 2 points this warp serves
    const int lbase = (warp & 1) * 8;   // neighbor offset within the point
    float* wl_pt = wlog + ppt * 192;

    for (int n0 = blockIdx.x * 2; n0 < NPTS; n0 += gridDim.x * 2) {
        __syncthreads();   // previous iteration fully consumed (hbuf/wlog)
        int n = n0 + ppt;

        float qr0 = g_query[n * CDIM + c0];
        float qr1 = g_query[n * CDIM + c1];
        float qr2 = g_query[n * CDIM + c2];
        float px = xyz[n * 3], py = xyz[n * 3 + 1], pz = xyz[n * 3 + 2];

        int safe[8]; float mk[8];
#pragma unroll
        for (int ss = 0; ss < 8; ss++) {
            int idx = refidx[n * SNBR + lbase + ss];
            mk[ss]  = (idx >= 0) ? 1.0f : 0.0f;
            safe[ss] = (idx >= 0) ? idx : 0;
        }
        // k-gather prefetch: in flight during phase 1 + 2
        float kgA[8], kgB[8], kgC[8];
#pragma unroll
        for (int ss = 0; ss < 8; ss++) {
            kgA[ss] = g_keyf[safe[ss] * CDIM + c0];
            kgB[ss] = g_keyf[safe[ss] * CDIM + c1];
            kgC[ss] = g_keyf[safe[ss] * CDIM + c2];
        }

        // phase 1: h = relu(ln(pos@Wp1+bp1)) for 8 neighbors -> hb
#pragma unroll
        for (int ss = 0; ss < 8; ss++) {
            int sf = safe[ss]; float m = mk[ss];
            float p0 = (xyz[sf * 3]     - px) * m;
            float p1 = (xyz[sf * 3 + 1] - py) * m;
            float p2 = (xyz[sf * 3 + 2] - pz) * m;
            float t0 = fmaf(p0, w1_00, fmaf(p1, w1_10, fmaf(p2, w1_20, bb0)));
            float t1 = fmaf(p0, w1_01, fmaf(p1, w1_11, fmaf(p2, w1_21, bb1)));
            float t2 = fmaf(p0, w1_02, fmaf(p1, w1_12, fmaf(p2, w1_22, bb2)));
            float mu = warp_sum32(t0 + t1 + t2) * (1.0f / 96.0f);
            float e0 = t0 - mu, e1 = t1 - mu, e2 = t2 - mu;
            float var = warp_sum32(e0*e0 + e1*e1 + e2*e2) * (1.0f / 96.0f);
            float rs = rsqrtf(var + EPSF);
            hb[ss * 96 + c0] = fmaxf(fmaf(e0 * rs, gp0, be0), 0.0f);
            hb[ss * 96 + c1] = fmaxf(fmaf(e1 * rs, gp1, be1), 0.0f);
            hb[ss * 96 + c2] = fmaxf(fmaf(e2 * rs, gp2, be2), 0.0f);
        }
        __syncwarp();

        // phase 2: batched peb matvec, weight reuse x8
        float a0[8] = {0,0,0,0,0,0,0,0};
        float a1[8] = {0,0,0,0,0,0,0,0};
        float a2[8] = {0,0,0,0,0,0,0,0};
#pragma unroll 6
        for (int j4 = 0; j4 < 24; j4++) {
            float4 u0 = W0[j4], u1 = W1[j4], u2 = W2[j4];
#pragma unroll
            for (int ss = 0; ss < 8; ss++) {
                float4 h = hb4[ss * 24 + j4];
                a0[ss] = d4(u0, h, a0[ss]);
                a1[ss] = d4(u1, h, a1[ss]);
                a2[ss] = d4(u2, h, a2[ss]);
            }
        }
        __syncwarp();   // hb reads done before rel overwrite

        // v-gather burst (MLP-pipelined), then epilogue
        float vgA[8], vgB[8], vgC[8];
#pragma unroll
        for (int ss = 0; ss < 8; ss++) {
            vgA[ss] = g_val[safe[ss] * CDIM + c0];
            vgB[ss] = g_val[safe[ss] * CDIM + c1];
            vgC[ss] = g_val[safe[ss] * CDIM + c2];
        }
        float vp0[8], vp1[8], vp2[8];
#pragma unroll
        for (int ss = 0; ss < 8; ss++) {
            float m = mk[ss];
            float peb0 = a0[ss] + b20, peb1 = a1[ss] + b21, peb2 = a2[ss] + b22;
            hb[ss * 96 + c0] = fmaf(kgA[ss], m, -qr0) + peb0;
            hb[ss * 96 + c1] = fmaf(kgB[ss], m, -qr1) + peb1;
            hb[ss * 96 + c2] = fmaf(kgC[ss], m, -qr2) + peb2;
            vp0[ss] = fmaf(vgA[ss], m, peb0);
            vp1[ss] = fmaf(vgB[ss], m, peb1);
            vp2[ss] = fmaf(vgC[ss], m, peb2);
        }
        __syncwarp();

        // phase 3: w-logits, both half-warps active, 2 neighbors per pass
#pragma unroll
        for (int pass = 0; pass < 4; pass++) {
            int sl = pass * 2 + (halfbit >> 4);
            float u0 = 0, u1 = 0, u2 = 0, u3 = 0;
            if (act) {
                const float4* Wg = (const float4*)(Ww1t + gl * 100);
                const float4* rv = hb4 + sl * 24;
#pragma unroll 6
                for (int j4 = 0; j4 < 24; j4++) {
                    float4 r = rv[j4], w = Wg[j4];
                    u0 = fmaf(w.x, r.x, u0); u1 = fmaf(w.y, r.y, u1);
                    u2 = fmaf(w.z, r.z, u2); u3 = fmaf(w.w, r.w, u3);
                }
            }
            float uacc = act ? (u0 + u1 + u2 + u3 + bw1r) : 0.0f;
            float mug = group_sum16(uacc) * (1.0f / 12.0f);
            float df = act ? (uacc - mug) : 0.0f;
            float varg = group_sum16(df * df) * (1.0f / 12.0f);
            float rsg = rsqrtf(varg + EPSF);
            float aval = act ? fmaxf(fmaf(df * rsg, gwr, bewr), 0.0f) : 0.0f;
            float wl = bw2r;
#pragma unroll
            for (int hh = 0; hh < 12; hh++) {
                float av = __shfl_sync(0xffffffffu, aval, halfbit | hh);
                wl = fmaf(av, SWW2(hh * 12 + gidx), wl);
            }
            if (act) wl_pt[(lbase + sl) * 12 + gl] = wl;
        }
        __syncthreads();

        // softmax over 16 neighbors per (point, group), * mask
        if (tid < 24) {
            int p = tid / 12, g = tid % 12;
            int nn = n0 + p;
            float* wp = wlog + p * 192;
            float m = -1e30f;
#pragma unroll
            for (int s = 0; s < SNBR; s++) m = fmaxf(m, wp[s * 12 + g]);
            float e[SNBR]; float sumv = 0.0f;
#pragma unroll
            for (int s = 0; s < SNBR; s++) { e[s] = expf(wp[s * 12 + g] - m); sumv += e[s]; }
            float inv = 1.0f / sumv;
#pragma unroll
            for (int s = 0; s < SNBR; s++) {
                float msk = (refidx[nn * SNBR + s] >= 0) ? 1.0f : 0.0f;
                wp[s * 12 + g] = e[s] * inv * msk;
            }
        }
        __syncthreads();

        // per-warp partial einsum over its 8 neighbors
        float f0 = 0, f1 = 0, f2 = 0;
#pragma unroll
        for (int ss = 0; ss < 8; ss++) {
            f0 = fmaf(vp0[ss], wl_pt[(lbase + ss) * 12 + g0], f0);
            f1 = fmaf(vp1[ss], wl_pt[(lbase + ss) * 12 + g1], f1);
            f2 = fmaf(vp2[ss], wl_pt[(lbase + ss) * 12 + g2], f2);
        }
        hb[c0] = f0; hb[c1] = f1; hb[c2] = f2;   // reuse hbuf as partial buffer
        __syncthreads();

        // combine warp pairs, write both points
        for (int i = tid; i < 192; i += 128) {
            int p = i / 96, c = i % 96;
            out[(n0 + p) * CDIM + c] = hbuf[(p * 2) * 768 + c] + hbuf[(p * 2 + 1) * 768 + c];
        }
    }
}

// ---------------------------------------------------------------------------
extern "C" void kernel_launch(void* const* d_in, const int* in_sizes, int n_in,
                              void* d_out, int out_size) {
    const float* q     = (const float*)d_in[0];
    const float* k     = (const float*)d_in[1];
    const float* v     = (const float*)d_in[2];
    const float* xyz   = (const float*)d_in[3];
    const int*   ridx  = (const int*)  d_in[4];
    const float* Wq    = (const float*)d_in[5];
    const float* bq    = (const float*)d_in[6];
    const float* gq    = (const float*)d_in[7];
    const float* betaq = (const float*)d_in[8];
    const float* Wk    = (const float*)d_in[9];
    const float* bk    = (const float*)d_in[10];
    const float* gk    = (const float*)d_in[11];
    const float* betak = (const float*)d_in[12];
    const float* Wv    = (const float*)d_in[13];
    const float* bv    = (const float*)d_in[14];
    const float* Wp1   = (const float*)d_in[15];
    const float* bp1   = (const float*)d_in[16];
    const float* gp    = (const float*)d_in[17];
    const float* betap = (const float*)d_in[18];
    const float* Wp2   = (const float*)d_in[19];
    const float* bp2   = (const float*)d_in[20];
    const float* Ww1   = (const float*)d_in[21];
    const float* bw1   = (const float*)d_in[22];
    const float* gw    = (const float*)d_in[23];
    const float* betaw = (const float*)d_in[24];
    const float* Ww2   = (const float*)d_in[25];
    const float* bw2   = (const float*)d_in[26];
    float* out = (float*)d_out;

    size_t smemA = (size_t)12960 * sizeof(float);          // 51,840 B
    size_t smemB = (size_t)SMEMB_FLOATS * sizeof(float);   // 57,024 B
    cudaFuncSetAttribute(proj_kernel, cudaFuncAttributeMaxDynamicSharedMemorySize, (int)smemA);
    cudaFuncSetAttribute(attn_kernel, cudaFuncAttributeMaxDynamicSharedMemorySize, (int)smemB);

    proj_kernel<<<444, 256, smemA>>>(q, k, v, Wq, bq, gq, betaq, Wk, bk, gk, betak, Wv, bv);
    attn_kernel<<<592, 128, smemB>>>(xyz, ridx, Wp1, bp1, gp, betap, Wp2, bp2,
                                     Ww1, bw1, gw, betaw, Ww2, bw2, out);
}

// round 9
// speedup vs baseline: 1.5862x; 1.1299x over previous
#include <cuda_runtime.h>
#include <math.h>

#define NPTS 40000
#define SNBR 16
#define CDIM 96
#define GDIM 12
#define EPSF 1e-5f

// Scratch (device globals: no allocation allowed)
__device__ float g_query[NPTS * CDIM];
__device__ float g_keyf [NPTS * CDIM];
__device__ float g_val  [NPTS * CDIM];
__device__ float g_kw   [NPTS * GDIM];   // keyf @ Ww1
__device__ float g_qw   [NPTS * GDIM];   // query @ Ww1

typedef unsigned long long ull;

__device__ __forceinline__ float warp_sum32(float v) {
    v += __shfl_xor_sync(0xffffffffu, v, 16);
    v += __shfl_xor_sync(0xffffffffu, v, 8);
    v += __shfl_xor_sync(0xffffffffu, v, 4);
    v += __shfl_xor_sync(0xffffffffu, v, 2);
    v += __shfl_xor_sync(0xffffffffu, v, 1);
    return v;
}
__device__ __forceinline__ float group_sum16(float v) {
    v += __shfl_xor_sync(0xffffffffu, v, 8);
    v += __shfl_xor_sync(0xffffffffu, v, 4);
    v += __shfl_xor_sync(0xffffffffu, v, 2);
    v += __shfl_xor_sync(0xffffffffu, v, 1);
    return v;
}
__device__ __forceinline__ float d4(float4 u, float4 x, float a) {
    return fmaf(u.x, x.x, fmaf(u.y, x.y, fmaf(u.z, x.z, fmaf(u.w, x.w, a))));
}
// f32x2 packed helpers
__device__ __forceinline__ ull pk2(float w) {
    ull r; asm("mov.b64 %0, {%1, %1};" : "=l"(r) : "f"(w)); return r;
}
__device__ __forceinline__ void fma2(ull &d, ull a, ull b) {
    asm("fma.rn.f32x2 %0, %1, %2, %0;" : "+l"(d) : "l"(a), "l"(b));
}
__device__ __forceinline__ void unpk2(float &lo, float &hi, ull v) {
    asm("mov.b64 {%0, %1}, %2;" : "=f"(lo), "=f"(hi) : "l"(v));
}

// ---------------------------------------------------------------------------
// Kernel A: q/k/v projections (unchanged from round 8).
// ---------------------------------------------------------------------------
__device__ __forceinline__ void proj_batch4(
    const float* __restrict__ src, float* __restrict__ dst,
    const float* Wt, const float* bias, const float* gain, const float* beta,
    float* xb, int base, int lane, bool do_ln)
{
    const int c0 = lane, c1 = lane + 32, c2 = lane + 64;
    bool ok[4];
#pragma unroll
    for (int r = 0; r < 4; r++) {
        int row = base + r;
        ok[r] = row < NPTS;
        if (ok[r]) {
            xb[r * 96 + c0] = src[row * CDIM + c0];
            xb[r * 96 + c1] = src[row * CDIM + c1];
            xb[r * 96 + c2] = src[row * CDIM + c2];
        }
    }
    __syncwarp();
    const float4* xb4 = (const float4*)xb;
    const float4* W0 = (const float4*)(Wt + c0 * 100);
    const float4* W1 = (const float4*)(Wt + c1 * 100);
    const float4* W2 = (const float4*)(Wt + c2 * 100);
    float a0[4] = {0,0,0,0}, a1[4] = {0,0,0,0}, a2[4] = {0,0,0,0};
#pragma unroll
    for (int j4 = 0; j4 < 24; j4++) {
        float4 x0 = xb4[j4], x1 = xb4[24 + j4], x2 = xb4[48 + j4], x3 = xb4[72 + j4];
        float4 u = W0[j4];
        a0[0] = d4(u, x0, a0[0]); a0[1] = d4(u, x1, a0[1]);
        a0[2] = d4(u, x2, a0[2]); a0[3] = d4(u, x3, a0[3]);
        u = W1[j4];
        a1[0] = d4(u, x0, a1[0]); a1[1] = d4(u, x1, a1[1]);
        a1[2] = d4(u, x2, a1[2]); a1[3] = d4(u, x3, a1[3]);
        u = W2[j4];
        a2[0] = d4(u, x0, a2[0]); a2[1] = d4(u, x1, a2[1]);
        a2[2] = d4(u, x2, a2[2]); a2[3] = d4(u, x3, a2[3]);
    }
    __syncwarp();
#pragma unroll
    for (int r = 0; r < 4; r++) {
        float y0 = a0[r] + bias[c0];
        float y1 = a1[r] + bias[c1];
        float y2 = a2[r] + bias[c2];
        if (do_ln) {
            float mu = warp_sum32(y0 + y1 + y2) * (1.0f / 96.0f);
            float e0 = y0 - mu, e1 = y1 - mu, e2 = y2 - mu;
            float var = warp_sum32(e0*e0 + e1*e1 + e2*e2) * (1.0f / 96.0f);
            float rs = rsqrtf(var + EPSF);
            y0 = fmaxf(fmaf(e0 * rs, gain[c0], beta[c0]), 0.0f);
            y1 = fmaxf(fmaf(e1 * rs, gain[c1], beta[c1]), 0.0f);
            y2 = fmaxf(fmaf(e2 * rs, gain[c2], beta[c2]), 0.0f);
        }
        if (ok[r]) {
            int row = base + r;
            dst[row * CDIM + c0] = y0;
            dst[row * CDIM + c1] = y1;
            dst[row * CDIM + c2] = y2;
        }
    }
}

__global__ void __launch_bounds__(256, 3) proj_kernel(
    const float* __restrict__ q, const float* __restrict__ k, const float* __restrict__ v,
    const float* __restrict__ Wq, const float* __restrict__ bq,
    const float* __restrict__ gq, const float* __restrict__ betaq,
    const float* __restrict__ Wk, const float* __restrict__ bk,
    const float* __restrict__ gk, const float* __restrict__ betak,
    const float* __restrict__ Wv, const float* __restrict__ bv)
{
    extern __shared__ float sm[];
    float* Wt  = sm;            // 9600
    float* prm = sm + 9600;     // 288
    float* xst = sm + 9888;     // 8 warps * 384

    int type = blockIdx.x / 148;   // 0=q, 1=k, 2=v
    int blk  = blockIdx.x % 148;
    const float *src, *W, *bias, *gain, *beta;
    float* dst;
    bool do_ln;
    if (type == 0) { src = q; W = Wq; bias = bq; gain = gq; beta = betaq; dst = g_query; do_ln = true;  }
    else if (type == 1) { src = k; W = Wk; bias = bk; gain = gk; beta = betak; dst = g_keyf; do_ln = true;  }
    else { src = v; W = Wv; bias = bv; gain = bv; beta = bv; dst = g_val; do_ln = false; }

    int tid = threadIdx.x;
    for (int i = tid; i < 9216; i += 256) {
        int j = i / 96, c = i % 96;
        Wt[c * 100 + j] = W[i];
    }
    for (int i = tid; i < 96; i += 256) {
        prm[i]       = bias[i];
        prm[96 + i]  = do_ln ? gain[i] : 0.0f;
        prm[192 + i] = do_ln ? beta[i] : 0.0f;
    }
    __syncthreads();

    int warp = tid >> 5, lane = tid & 31;
    float* xb = xst + warp * 384;

    for (int base = (blk * 8 + warp) * 4; base < NPTS; base += 148 * 8 * 4) {
        proj_batch4(src, dst, Wt, prm, prm + 96, prm + 192, xb, base, lane, do_ln);
    }
}

// ---------------------------------------------------------------------------
// Kernel A2: K_w = keyf @ Ww1, Q_w = query @ Ww1   (runs after proj)
// ---------------------------------------------------------------------------
__global__ void __launch_bounds__(256) kw_kernel(const float* __restrict__ Ww1)
{
    __shared__ float W[96 * 13];   // padded stride 13: conflict-free
    int tid = threadIdx.x;
    for (int i = tid; i < 1152; i += 256) {
        int c = i / 12, g = i % 12;
        W[c * 13 + g] = Ww1[i];
    }
    __syncthreads();

    int warp = tid >> 5, lane = tid & 31;
    const int c0 = lane, c1 = lane + 32, c2 = lane + 64;
    int gwid = blockIdx.x * 8 + warp;
    int nw = gridDim.x * 8;

    for (int row = gwid; row < NPTS; row += nw) {
#pragma unroll
        for (int which = 0; which < 2; which++) {
            const float* srcb = which ? g_query : g_keyf;
            float* dstb = which ? g_qw : g_kw;
            float y0 = srcb[row * CDIM + c0];
            float y1 = srcb[row * CDIM + c1];
            float y2 = srcb[row * CDIM + c2];
            float p[12];
#pragma unroll
            for (int g = 0; g < 12; g++)
                p[g] = fmaf(y0, W[c0 * 13 + g], fmaf(y1, W[c1 * 13 + g], y2 * W[c2 * 13 + g]));
#pragma unroll
            for (int g = 0; g < 12; g++) p[g] = warp_sum32(p[g]);
            float kv = p[0];
#pragma unroll
            for (int g = 1; g < 12; g++) if (lane == g) kv = p[g];
            if (lane < 12) dstb[row * GDIM + lane] = kv;
        }
    }
}

// ---------------------------------------------------------------------------
// Kernel B: fused grouped vector attention with f32x2 packed peb matvec and
// decomposed w-logits (u = mk*K_w[safe] - Q_w + h@M + c2).
// smem (floats): Wp2t 9600 (Ww2 in row padding) | Mt 1200 (c2 in padding) |
//   wlog 384 | hbuf 3072 = 14,256 floats = 57,024 B -> 4 blocks/SM.
// hbuf per warp: hbA[96][4] (ss0..3) + hbB[96][4] (ss4..7) = 768 floats.
// ---------------------------------------------------------------------------
#define SMEMB_FLOATS 14256
#define SWW2(i) sm[(((i) >> 1) * 100) + 96 + ((i) & 1)]
#define SC2(g)  sm[9600 + (g) * 100 + 96]

__global__ void __launch_bounds__(128, 4) attn_kernel(
    const float* __restrict__ xyz, const int* __restrict__ refidx,
    const float* __restrict__ Wp1, const float* __restrict__ bp1,
    const float* __restrict__ gp,  const float* __restrict__ betap,
    const float* __restrict__ Wp2, const float* __restrict__ bp2,
    const float* __restrict__ Ww1, const float* __restrict__ bw1,
    const float* __restrict__ gw,  const float* __restrict__ betaw,
    const float* __restrict__ Ww2, const float* __restrict__ bw2,
    float* __restrict__ out)
{
    extern __shared__ float sm[];
    float* Wp2t  = sm;            // 9600  ([c][100], slots 96..97/row hold Ww2)
    float* Mt    = sm + 9600;     // 1200  ([g][100], slot 96/row holds c2)
    float* wlog  = sm + 10800;    // 2 points * 16 nbr * 12
    float* hbuf  = sm + 11184;    // 4 warps * 768

    int tid = threadIdx.x;
    for (int i = tid; i < 9216; i += 128) {
        int j = i / 96, c = i % 96;
        Wp2t[c * 100 + j] = Wp2[i];
    }
    for (int i = tid; i < 144; i += 128) SWW2(i) = Ww2[i];
    __syncthreads();

    // M[j][g] = sum_c Wp2[j][c] * Ww1[c][g], stored Mt[g*100 + j]
    for (int i = tid; i < 1152; i += 128) {
        int g = i % 12, j = i / 12;
        float s = 0.0f;
        for (int c = 0; c < 96; c++)
            s = fmaf(Wp2t[c * 100 + j], __ldg(&Ww1[c * 12 + g]), s);
        Mt[g * 100 + j] = s;
    }
    // c2_g = bp2 @ Ww1[:,g] + bw1_g
    if (tid < 12) {
        float s = bw1[tid];
        for (int c = 0; c < 96; c++)
            s = fmaf(__ldg(&bp2[c]), __ldg(&Ww1[c * 12 + tid]), s);
        SC2(tid) = s;
    }
    __syncthreads();

    int warp = tid >> 5, lane = tid & 31;
    const int c0 = lane, c1 = lane + 32, c2 = lane + 64;
    float* hbA = hbuf + warp * 768;        // [96][4] ss0..3
    float* hbB = hbA + 384;                // [96][4] ss4..7
    const double2* hA2 = (const double2*)hbA;
    const double2* hB2 = (const double2*)hbB;
    const float4* W0 = (const float4*)(Wp2t + c0 * 100);
    const float4* W1 = (const float4*)(Wp2t + c1 * 100);
    const float4* W2 = (const float4*)(Wp2t + c2 * 100);

    const int gl = lane & 15;
    const bool act = gl < 12;
    const int gidx = act ? gl : 0;
    const int halfbit = lane & 16;
    const float4* WM = (const float4*)(Mt + gidx * 100);

    // per-lane invariants
    float w1_00 = Wp1[c0],      w1_10 = Wp1[96 + c0], w1_20 = Wp1[192 + c0];
    float w1_01 = Wp1[c1],      w1_11 = Wp1[96 + c1], w1_21 = Wp1[192 + c1];
    float w1_02 = Wp1[c2],      w1_12 = Wp1[96 + c2], w1_22 = Wp1[192 + c2];
    float bb0 = bp1[c0],  bb1 = bp1[c1],  bb2 = bp1[c2];
    float gp0 = gp[c0],   gp1 = gp[c1],   gp2 = gp[c2];
    float be0 = betap[c0],be1 = betap[c1],be2 = betap[c2];
    float b20 = bp2[c0],  b21 = bp2[c1],  b22 = bp2[c2];
    const int g0 = c0 >> 3, g1 = c1 >> 3, g2 = c2 >> 3;
    float gwr = gw[gidx], bewr = betaw[gidx], bw2r = bw2[gidx];
    float c2g = SC2(gidx);

    const int ppt   = warp >> 1;        // point within pair
    const int lbase = (warp & 1) * 8;   // neighbor offset
    float* wl_pt = wlog + ppt * 192;

    for (int n0 = blockIdx.x * 2; n0 < NPTS; n0 += gridDim.x * 2) {
        __syncthreads();
        int n = n0 + ppt;

        float qr0 = g_query[n * CDIM + c0];
        float qr1 = g_query[n * CDIM + c1];
        float qr2 = g_query[n * CDIM + c2];
        float qwv = g_qw[n * GDIM + gidx];
        float px = xyz[n * 3], py = xyz[n * 3 + 1], pz = xyz[n * 3 + 2];

        int safe[8]; float mk[8];
#pragma unroll
        for (int ss = 0; ss < 8; ss++) {
            int idx = refidx[n * SNBR + lbase + ss];
            mk[ss]  = (idx >= 0) ? 1.0f : 0.0f;
            safe[ss] = (idx >= 0) ? idx : 0;
        }
        // K_w gather (12 floats/neighbor) — in flight during phase 1+2
        float kwv[8];
#pragma unroll
        for (int ss = 0; ss < 8; ss++) kwv[ss] = g_kw[safe[ss] * GDIM + gidx];

        // phase 1: h = relu(ln(pos@Wp1+bp1)) -> paired smem layout
#pragma unroll
        for (int ss = 0; ss < 8; ss++) {
            int sf = safe[ss]; float m = mk[ss];
            float p0 = (xyz[sf * 3]     - px) * m;
            float p1 = (xyz[sf * 3 + 1] - py) * m;
            float p2 = (xyz[sf * 3 + 2] - pz) * m;
            float t0 = fmaf(p0, w1_00, fmaf(p1, w1_10, fmaf(p2, w1_20, bb0)));
            float t1 = fmaf(p0, w1_01, fmaf(p1, w1_11, fmaf(p2, w1_21, bb1)));
            float t2 = fmaf(p0, w1_02, fmaf(p1, w1_12, fmaf(p2, w1_22, bb2)));
            float mu = warp_sum32(t0 + t1 + t2) * (1.0f / 96.0f);
            float e0 = t0 - mu, e1 = t1 - mu, e2 = t2 - mu;
            float var = warp_sum32(e0*e0 + e1*e1 + e2*e2) * (1.0f / 96.0f);
            float rs = rsqrtf(var + EPSF);
            float* dstp = (ss < 4 ? hbA : hbB) + (ss & 3);
            dstp[c0 * 4] = fmaxf(fmaf(e0 * rs, gp0, be0), 0.0f);
            dstp[c1 * 4] = fmaxf(fmaf(e1 * rs, gp1, be1), 0.0f);
            dstp[c2 * 4] = fmaxf(fmaf(e2 * rs, gp2, be2), 0.0f);
        }
        __syncwarp();

        // phase 2: packed f32x2 matvec — 3 peb rows + 1 fused h@M row
        ull ac0[4] = {0,0,0,0}, ac1[4] = {0,0,0,0}, ac2[4] = {0,0,0,0}, ac3[4] = {0,0,0,0};
#pragma unroll 4
        for (int j4 = 0; j4 < 24; j4++) {
            float4 w0 = W0[j4], w1 = W1[j4], w2 = W2[j4], wm = WM[j4];
            float w0a[4] = {w0.x, w0.y, w0.z, w0.w};
            float w1a[4] = {w1.x, w1.y, w1.z, w1.w};
            float w2a[4] = {w2.x, w2.y, w2.z, w2.w};
            float wma[4] = {wm.x, wm.y, wm.z, wm.w};
#pragma unroll
            for (int t = 0; t < 4; t++) {
                int cc = 4 * j4 + t;
                double2 pa = hA2[cc];
                double2 pb = hB2[cc];
                ull h01 = __double_as_longlong(pa.x);
                ull h23 = __double_as_longlong(pa.y);
                ull h45 = __double_as_longlong(pb.x);
                ull h67 = __double_as_longlong(pb.y);
                ull wp;
                wp = pk2(w0a[t]);
                fma2(ac0[0], h01, wp); fma2(ac0[1], h23, wp);
                fma2(ac0[2], h45, wp); fma2(ac0[3], h67, wp);
                wp = pk2(w1a[t]);
                fma2(ac1[0], h01, wp); fma2(ac1[1], h23, wp);
                fma2(ac1[2], h45, wp); fma2(ac1[3], h67, wp);
                wp = pk2(w2a[t]);
                fma2(ac2[0], h01, wp); fma2(ac2[1], h23, wp);
                fma2(ac2[2], h45, wp); fma2(ac2[3], h67, wp);
                wp = pk2(wma[t]);
                fma2(ac3[0], h01, wp); fma2(ac3[1], h23, wp);
                fma2(ac3[2], h45, wp); fma2(ac3[3], h67, wp);
            }
        }
        float a0[8], a1[8], a2[8], a3[8];
#pragma unroll
        for (int sp = 0; sp < 4; sp++) {
            unpk2(a0[2*sp], a0[2*sp+1], ac0[sp]);
            unpk2(a1[2*sp], a1[2*sp+1], ac1[sp]);
            unpk2(a2[2*sp], a2[2*sp+1], ac2[sp]);
            unpk2(a3[2*sp], a3[2*sp+1], ac3[sp]);
        }

        // v-gather burst, then vp = val*mk + peb
        float vgA[8], vgB[8], vgC[8];
#pragma unroll
        for (int ss = 0; ss < 8; ss++) {
            vgA[ss] = g_val[safe[ss] * CDIM + c0];
            vgB[ss] = g_val[safe[ss] * CDIM + c1];
            vgC[ss] = g_val[safe[ss] * CDIM + c2];
        }
        float vp0[8], vp1[8], vp2[8];
#pragma unroll
        for (int ss = 0; ss < 8; ss++) {
            float m = mk[ss];
            vp0[ss] = fmaf(vgA[ss], m, a0[ss] + b20);
            vp1[ss] = fmaf(vgB[ss], m, a1[ss] + b21);
            vp2[ss] = fmaf(vgC[ss], m, a2[ss] + b22);
        }

        // w-logits: u = mk*K_w - Q_w + h@M + c2, then LN + relu + @Ww2
#pragma unroll
        for (int pass = 0; pass < 4; pass++) {
            int sl = 2 * pass + (halfbit >> 4);
            float uacc, mkv;
            if (halfbit) { uacc = a3[2*pass+1]; mkv = mk[2*pass+1]; }
            else         { uacc = a3[2*pass];   mkv = mk[2*pass];   }
            float kwq;
            if (halfbit) kwq = kwv[2*pass+1]; else kwq = kwv[2*pass];
            uacc = act ? (fmaf(mkv, kwq, uacc) - qwv + c2g) : 0.0f;
            float mug = group_sum16(uacc) * (1.0f / 12.0f);
            float df = act ? (uacc - mug) : 0.0f;
            float varg = group_sum16(df * df) * (1.0f / 12.0f);
            float rsg = rsqrtf(varg + EPSF);
            float aval = act ? fmaxf(fmaf(df * rsg, gwr, bewr), 0.0f) : 0.0f;
            float wl = bw2r;
#pragma unroll
            for (int hh = 0; hh < 12; hh++) {
                float av = __shfl_sync(0xffffffffu, aval, halfbit | hh);
                wl = fmaf(av, SWW2(hh * 12 + gidx), wl);
            }
            if (act) wl_pt[(lbase + sl) * 12 + gl] = wl;
        }
        __syncthreads();

        // softmax over 16 neighbors per (point, group), * mask
        if (tid < 24) {
            int p = tid / 12, g = tid % 12;
            int nn = n0 + p;
            float* wp = wlog + p * 192;
            float m = -1e30f;
#pragma unroll
            for (int s = 0; s < SNBR; s++) m = fmaxf(m, wp[s * 12 + g]);
            float e[SNBR]; float sumv = 0.0f;
#pragma unroll
            for (int s = 0; s < SNBR; s++) { e[s] = expf(wp[s * 12 + g] - m); sumv += e[s]; }
            float inv = 1.0f / sumv;
#pragma unroll
            for (int s = 0; s < SNBR; s++) {
                float msk = (refidx[nn * SNBR + s] >= 0) ? 1.0f : 0.0f;
                wp[s * 12 + g] = e[s] * inv * msk;
            }
        }
        __syncthreads();

        // per-warp partial einsum, combine warp pairs
        float f0 = 0, f1 = 0, f2 = 0;
#pragma unroll
        for (int ss = 0; ss < 8; ss++) {
            f0 = fmaf(vp0[ss], wl_pt[(lbase + ss) * 12 + g0], f0);
            f1 = fmaf(vp1[ss], wl_pt[(lbase + ss) * 12 + g1], f1);
            f2 = fmaf(vp2[ss], wl_pt[(lbase + ss) * 12 + g2], f2);
        }
        hbA[c0] = f0; hbA[c1] = f1; hbA[c2] = f2;
        __syncthreads();

        for (int i = tid; i < 192; i += 128) {
            int p = i / 96, c = i % 96;
            out[(n0 + p) * CDIM + c] = hbuf[(p * 2) * 768 + c] + hbuf[(p * 2 + 1) * 768 + c];
        }
    }
}

// ---------------------------------------------------------------------------
extern "C" void kernel_launch(void* const* d_in, const int* in_sizes, int n_in,
                              void* d_out, int out_size) {
    const float* q     = (const float*)d_in[0];
    const float* k     = (const float*)d_in[1];
    const float* v     = (const float*)d_in[2];
    const float* xyz   = (const float*)d_in[3];
    const int*   ridx  = (const int*)  d_in[4];
    const float* Wq    = (const float*)d_in[5];
    const float* bq    = (const float*)d_in[6];
    const float* gq    = (const float*)d_in[7];
    const float* betaq = (const float*)d_in[8];
    const float* Wk    = (const float*)d_in[9];
    const float* bk    = (const float*)d_in[10];
    const float* gk    = (const float*)d_in[11];
    const float* betak = (const float*)d_in[12];
    const float* Wv    = (const float*)d_in[13];
    const float* bv    = (const float*)d_in[14];
    const float* Wp1   = (const float*)d_in[15];
    const float* bp1   = (const float*)d_in[16];
    const float* gp    = (const float*)d_in[17];
    const float* betap = (const float*)d_in[18];
    const float* Wp2   = (const float*)d_in[19];
    const float* bp2   = (const float*)d_in[20];
    const float* Ww1   = (const float*)d_in[21];
    const float* bw1   = (const float*)d_in[22];
    const float* gw    = (const float*)d_in[23];
    const float* betaw = (const float*)d_in[24];
    const float* Ww2   = (const float*)d_in[25];
    const float* bw2   = (const float*)d_in[26];
    float* out = (float*)d_out;

    size_t smemA = (size_t)12960 * sizeof(float);          // 51,840 B
    size_t smemB = (size_t)SMEMB_FLOATS * sizeof(float);   // 57,024 B
    cudaFuncSetAttribute(proj_kernel, cudaFuncAttributeMaxDynamicSharedMemorySize, (int)smemA);
    cudaFuncSetAttribute(attn_kernel, cudaFuncAttributeMaxDynamicSharedMemorySize, (int)smemB);

    proj_kernel<<<444, 256, smemA>>>(q, k, v, Wq, bq, gq, betaq, Wk, bk, gk, betak, Wv, bv);
    kw_kernel<<<296, 256>>>(Ww1);
    attn_kernel<<<592, 128, smemB>>>(xyz, ridx, Wp1, bp1, gp, betap, Wp2, bp2,
                                     Ww1, bw1, gw, betaw, Ww2, bw2, out);
}